// round 6
// baseline (speedup 1.0000x reference)
#include <cuda_runtime.h>
#include <cuda_bf16.h>

typedef unsigned long long ULL;

// ---------------- f32x2 packed helpers (sm_100+) ----------------
__device__ __forceinline__ ULL ffma2(ULL a, ULL b, ULL c) {
    ULL d;
    asm("fma.rn.f32x2 %0, %1, %2, %3;" : "=l"(d) : "l"(a), "l"(b), "l"(c));
    return d;
}
__device__ __forceinline__ ULL fadd2(ULL a, ULL b) {
    ULL d;
    asm("add.rn.f32x2 %0, %1, %2;" : "=l"(d) : "l"(a), "l"(b));
    return d;
}
__device__ __forceinline__ ULL dup2(float w) {
    unsigned u = __float_as_uint(w);
    ULL d;
    asm("mov.b64 %0, {%1, %1};" : "=l"(d) : "r"(u));
    return d;
}
__device__ __forceinline__ ULL pack2(float lo, float hi) {
    ULL d;
    unsigned a = __float_as_uint(lo), b = __float_as_uint(hi);
    asm("mov.b64 %0, {%1, %2};" : "=l"(d) : "r"(a), "r"(b));
    return d;
}
__device__ __forceinline__ void unpack2(ULL v, float& lo, float& hi) {
    unsigned a, b;
    asm("mov.b64 {%0, %1}, %2;" : "=r"(a), "=r"(b) : "l"(v));
    lo = __uint_as_float(a);
    hi = __uint_as_float(b);
}

// Weights are pre-scaled by C = 2*log2(e), so the accumulator directly holds
// u = 2*log2(e)*a. tanh(a) = 1 - 2/(exp(2a)+1) = 1 - 2/(exp2(u)+1).
// Saturates exactly to +/-1 for large |a|. (Proven path: rel_err 2.3e-7.)
__device__ __forceinline__ float tanh_from_scaled(float u) {
    float e;
    asm("ex2.approx.f32 %0, %1;" : "=f"(e) : "f"(u));
    float r;
    asm("rcp.approx.f32 %0, %1;" : "=f"(r) : "f"(e + 1.0f));
    return fmaf(-2.0f, r, 1.0f);
}

// ---------------- config ----------------
// B=4096, T=2048, F=8, H=32, O=8
// One 32-thread block = one warp = 4 batch rows (2 f32x2 pairs).
// Lanes 0-15 own pair 0, lanes 16-31 own pair 1; each lane computes output
// rows llo and llo+16 (W_hh rows llo, llo+16 duplicated in registers).
// R6: input projection hoisted to chunk top (xpA/xpB register arrays) ->
// step loop is only the h-dependent work; the dense 128-FFMA2 xp block is
// 8-way independent and fills the co-resident warp's latency bubbles.
#define TT    2048
#define FF    8
#define HH    32
#define OO    8
#define CHUNK 8       // timesteps of x staged per SMEM refill
#define HPAD  34      // ULL stride between pair h buffers (+4 banks)
#define XPAD  66      // ULL stride between pair x buffers (+4 banks)

__global__ void __launch_bounds__(32, 7)
rnn_fused_kernel(const float* __restrict__ x,
                 const float* __restrict__ W_ih,
                 const float* __restrict__ W_hh,
                 const float* __restrict__ b_ih,
                 const float* __restrict__ b_hh,
                 const float* __restrict__ W_out,
                 const float* __restrict__ b_out,
                 float* __restrict__ out)
{
    // Double-buffered h and x-chunk staging, per pair, interleaved (rowA,rowB).
    __shared__ __align__(16) ULL hb[2][2][HPAD];  // [buf][pair][32 + pad]
    __shared__ __align__(16) ULL xb[2][2][XPAD];  // [buf][pair][64 + pad]

    const int lane = threadIdx.x;       // 0..31
    const int llo  = lane & 15;
    const int half = lane >> 4;         // which pair this lane processes
    const size_t base = (size_t)blockIdx.x * 4;  // first of 4 batch rows

    const float C = 2.885390081777927f; // 2*log2(e), folded into weights

    // ---- weights into registers: W_hh rows llo and llo+16, scaled, dup'd ----
    ULL wA[HH], wB[HH];
    {
        const float4* ra = (const float4*)(W_hh + llo * HH);
        const float4* rb = (const float4*)(W_hh + (llo + 16) * HH);
        #pragma unroll
        for (int k = 0; k < HH / 4; ++k) {
            float4 va = ra[k], vb = rb[k];
            wA[4*k+0] = dup2(C*va.x); wA[4*k+1] = dup2(C*va.y);
            wA[4*k+2] = dup2(C*va.z); wA[4*k+3] = dup2(C*va.w);
            wB[4*k+0] = dup2(C*vb.x); wB[4*k+1] = dup2(C*vb.y);
            wB[4*k+2] = dup2(C*vb.z); wB[4*k+3] = dup2(C*vb.w);
        }
    }
    ULL wihA[FF], wihB[FF];
    {
        const float4* ra = (const float4*)(W_ih + llo * FF);
        const float4* rb = (const float4*)(W_ih + (llo + 16) * FF);
        #pragma unroll
        for (int k = 0; k < FF / 4; ++k) {
            float4 va = ra[k], vb = rb[k];
            wihA[4*k+0] = dup2(C*va.x); wihA[4*k+1] = dup2(C*va.y);
            wihA[4*k+2] = dup2(C*va.z); wihA[4*k+3] = dup2(C*va.w);
            wihB[4*k+0] = dup2(C*vb.x); wihB[4*k+1] = dup2(C*vb.y);
            wihB[4*k+2] = dup2(C*vb.z); wihB[4*k+3] = dup2(C*vb.w);
        }
    }
    const ULL biasA = dup2(C * (b_ih[llo]      + b_hh[llo]));
    const ULL biasB = dup2(C * (b_ih[llo + 16] + b_hh[llo + 16]));

    // h0 = 0 for both pairs
    hb[0][half][llo]      = 0ULL;
    hb[0][half][llo + 16] = 0ULL;

    // ---- x chunk prefetch: 4 rows x 64 floats = 64 float4, 2 per lane ----
    float4 pre0, pre1;
    {
        const int i0 = lane, i1 = lane + 32;
        const float* p0 = x + (base + (i0 >> 4)) * (size_t)(TT * FF) + (i0 & 15) * 4;
        const float* p1 = x + (base + (i1 >> 4)) * (size_t)(TT * FF) + (i1 & 15) * 4;
        pre0 = *(const float4*)p0;
        pre1 = *(const float4*)p1;
    }

    const int NCHUNK = TT / CHUNK;   // 256
    for (int c = 0; c < NCHUNK; ++c) {
        // stage prefetched chunk: interleaved (rowEven, rowOdd) per pair
        {
            const int buf = c & 1;
            #pragma unroll
            for (int k = 0; k < 2; ++k) {
                const int i    = lane + 32 * k;
                const int row  = i >> 4;
                const int pos  = i & 15;
                const int pair = row >> 1;
                const int slot = row & 1;
                float*  xs = (float*)&xb[buf][pair][0];
                const float4 v = (k == 0) ? pre0 : pre1;
                xs[(pos*4 + 0) * 2 + slot] = v.x;
                xs[(pos*4 + 1) * 2 + slot] = v.y;
                xs[(pos*4 + 2) * 2 + slot] = v.z;
                xs[(pos*4 + 3) * 2 + slot] = v.w;
            }
        }
        if (c + 1 < NCHUNK) {
            const int i0 = lane, i1 = lane + 32;
            const float* p0 = x + (base + (i0 >> 4)) * (size_t)(TT * FF)
                                + (size_t)(c + 1) * (CHUNK * FF) + (i0 & 15) * 4;
            const float* p1 = x + (base + (i1 >> 4)) * (size_t)(TT * FF)
                                + (size_t)(c + 1) * (CHUNK * FF) + (i1 & 15) * 4;
            pre0 = *(const float4*)p0;
            pre1 = *(const float4*)p1;
        }
        __syncwarp();

        // ---- chunk-top: input projection for all CHUNK steps (h-independent,
        // 8-way ILP; bias folded in). 128 dense FFMA2 per chunk. ----
        ULL xpA[CHUNK], xpB[CHUNK];
        #pragma unroll
        for (int s = 0; s < CHUNK; ++s) {
            const ULL* xr = &xb[c & 1][half][s * FF];
            ULL p0 = biasA, p1 = 0ULL;
            ULL q0 = biasB, q1 = 0ULL;
            #pragma unroll
            for (int f = 0; f < FF; f += 2) {
                ulonglong2 xv = *(const ulonglong2*)&xr[f];
                p0 = ffma2(xv.x, wihA[f],     p0);
                p1 = ffma2(xv.y, wihA[f + 1], p1);
                q0 = ffma2(xv.x, wihB[f],     q0);
                q1 = ffma2(xv.y, wihB[f + 1], q1);
            }
            xpA[s] = fadd2(p0, p1);
            xpB[s] = fadd2(q0, q1);
        }

        // ---- step loop: recurrent matvec + tanh only ----
        #pragma unroll
        for (int s = 0; s < CHUNK; ++s) {
            const int t = c * CHUNK + s;
            const ULL* hr = &hb[t & 1][half][0];

            ULL a0 = xpA[s], a1 = 0ULL;
            ULL c0 = xpB[s], c1 = 0ULL;

            #pragma unroll
            for (int j = 0; j < HH; j += 2) {
                ulonglong2 hv = *(const ulonglong2*)&hr[j];
                a0 = ffma2(hv.x, wA[j],     a0);
                a1 = ffma2(hv.y, wA[j + 1], a1);
                c0 = ffma2(hv.x, wB[j],     c0);
                c1 = ffma2(hv.y, wB[j + 1], c1);
            }
            const ULL accA = fadd2(a0, a1);
            const ULL accB = fadd2(c0, c1);

            float u0, u1, u2, u3;
            unpack2(accA, u0, u1);
            unpack2(accB, u2, u3);
            const float r0 = tanh_from_scaled(u0);
            const float r1 = tanh_from_scaled(u1);
            const float r2 = tanh_from_scaled(u2);
            const float r3 = tanh_from_scaled(u3);

            ULL* hw = &hb[(t + 1) & 1][half][0];
            hw[llo]      = pack2(r0, r1);
            hw[llo + 16] = pack2(r2, r3);
            __syncwarp();
        }
    }

    // ---- output head: y = h_final @ W_out^T + b_out ----
    // T=2048 even -> final h is in buffer 0; last __syncwarp already done.
    if (llo < OO) {
        const ULL* hf = &hb[0][half][0];
        float ya = b_out[llo];
        float yb = ya;
        #pragma unroll
        for (int j = 0; j < HH; ++j) {
            float ha, hc;
            unpack2(hf[j], ha, hc);
            const float wv = W_out[llo * HH + j];
            ya = fmaf(wv, ha, ya);
            yb = fmaf(wv, hc, yb);
        }
        const size_t r0 = base + 2 * half;
        out[r0 * OO + llo]       = ya;
        out[(r0 + 1) * OO + llo] = yb;
    }
}

extern "C" void kernel_launch(void* const* d_in, const int* in_sizes, int n_in,
                              void* d_out, int out_size)
{
    const float* x     = (const float*)d_in[0];
    const float* W_ih  = (const float*)d_in[1];
    const float* W_hh  = (const float*)d_in[2];
    const float* b_ih  = (const float*)d_in[3];
    const float* b_hh  = (const float*)d_in[4];
    const float* W_out = (const float*)d_in[5];
    const float* b_out = (const float*)d_in[6];
    float* out = (float*)d_out;

    // 4096 rows / 4 per warp = 1024 one-warp blocks (~7 per SM, one wave)
    rnn_fused_kernel<<<1024, 32>>>(x, W_ih, W_hh, b_ih, b_hh, W_out, b_out, out);
}